// round 17
// baseline (speedup 1.0000x reference)
#include <cuda_runtime.h>
#include <cuda_bf16.h>
#include <cstdint>

#define C_IN    64
#define K_OUT   64
#define H_IN    130
#define W_IN    130
#define H_OUT   128

// U in mma.sync B-fragment order: uint4 per (e, kslice, ks, lane) = {b0h,b1h,b0l,b1l}
__device__ uint4 g_Ufrag[36 * 8 * 4 * 32];   // 589 KB

__device__ const float d_ATx[24] = {
    1.f, 1.f,  1.f, 1.f,  1.f, 0.f,
    0.f, 1.f, -1.f, 2.f, -2.f, 0.f,
    0.f, 1.f,  1.f, 4.f,  4.f, 0.f,
    0.f, 1.f, -1.f, 8.f, -8.f, 1.f};
__device__ const float d_ATC[24] = {      // [y][b]
    1.f, 1.f,  1.f, 1.f,  1.f, 0.f,
    0.f, 1.f, -1.f, 2.f, -2.f, 0.f,
    0.f, 1.f,  1.f, 4.f,  4.f, 0.f,
    0.f, 1.f, -1.f, 8.f, -8.f, 1.f};
__device__ const float d_BT[36] = {
    4.f, 0.f, -5.f,  0.f, 1.f, 0.f,
    0.f,-4.f, -4.f,  1.f, 1.f, 0.f,
    0.f, 4.f, -4.f, -1.f, 1.f, 0.f,
    0.f,-2.f, -1.f,  2.f, 1.f, 0.f,
    0.f, 2.f, -1.f, -2.f, 1.f, 0.f,
    0.f, 4.f,  0.f, -5.f, 0.f, 1.f};

__device__ __forceinline__ uint32_t smem_u32(const void* p) {
    uint32_t a;
    asm("{ .reg .u64 t; cvta.to.shared.u64 t, %1; cvt.u32.u64 %0, t; }"
        : "=r"(a) : "l"(p));
    return a;
}

#define LDSM4(r, a)                                                          \
    asm volatile("ldmatrix.sync.aligned.m8n8.x4.shared.b16 {%0,%1,%2,%3}, [%4];" \
                 : "=r"((r)[0]), "=r"((r)[1]), "=r"((r)[2]), "=r"((r)[3])    \
                 : "r"(a))

#define MMA_BF16(c, a, b0, b1)                                               \
    asm volatile("mma.sync.aligned.m16n8k16.row.col.f32.bf16.bf16.f32 "      \
                 "{%0,%1,%2,%3},{%4,%5,%6,%7},{%8,%9},{%0,%1,%2,%3};"        \
                 : "+f"((c)[0]), "+f"((c)[1]), "+f"((c)[2]), "+f"((c)[3])    \
                 : "r"((a)[0]), "r"((a)[1]), "r"((a)[2]), "r"((a)[3]),       \
                   "r"(b0), "r"(b1))

// ---------------------------------------------------------------------------
// Kernel 1: filter transform -> g_Ufrag (fragment-order, hi/lo split)
// ---------------------------------------------------------------------------
__global__ void filter_transform(const float* __restrict__ w) {
    int c = threadIdx.x;
    int k = blockIdx.x;
    int a = blockIdx.y;

    constexpr float G[6][3] = {
        { 0.25f,     0.f,       0.f     },
        {-1.f/6.f,  -1.f/6.f,  -1.f/6.f },
        {-1.f/6.f,   1.f/6.f,  -1.f/6.f },
        { 1.f/24.f,  1.f/12.f,  1.f/6.f },
        { 1.f/24.f, -1.f/12.f,  1.f/6.f },
        { 0.f,       0.f,       1.f     }};

    const float* wp = w + (k * C_IN + c) * 9;
    float gw[3];
#pragma unroll
    for (int j = 0; j < 3; j++)
        gw[j] = G[a][0] * wp[0 * 3 + j] + G[a][1] * wp[1 * 3 + j] + G[a][2] * wp[2 * 3 + j];

    int wsl = k >> 3;
    int l   = (k & 7) * 4 + ((c & 7) >> 1);
    int ks  = c >> 4;
    int hh  = (c >> 3) & 1;
    int dd  = c & 1;
    unsigned short* ub = (unsigned short*)g_Ufrag;

#pragma unroll
    for (int b = 0; b < 6; b++) {
        float u = gw[0] * G[b][0] + gw[1] * G[b][1] + gw[2] * G[b][2];
        int e = a * 6 + b;
        size_t u4 = ((size_t)(e * 8 + wsl) * 4 + ks) * 32 + l;
        __nv_bfloat16 hi = __float2bfloat16_rn(u);
        __nv_bfloat16 lo = __float2bfloat16_rn(u - __bfloat162float(hi));
        ub[u4 * 8 + hh * 2 + dd]     = *(unsigned short*)&hi;
        ub[u4 * 8 + 4 + hh * 2 + dd] = *(unsigned short*)&lo;
    }
}

// ---------------------------------------------------------------------------
// Kernel 2: fully fused. CTA = 16p x 64k, 128 threads (4 warps x 16p x 16k).
// e-split: 18 transformed planes resident (72 KB), phase-1 runs twice.
// A rows packed: rows 0-7 = V_hi, 8-15 = V_lo (per 8-p group; 2 groups).
// ---------------------------------------------------------------------------
#define FUSED_SMEM 73728u

__global__ __launch_bounds__(128, 2) void winograd_fused(
        float* __restrict__ out, const float* __restrict__ x) {
    extern __shared__ __align__(128) char smem[];
    const uint32_t sb = smem_u32(smem);
    const int tid = threadIdx.x;
    const int lane = tid & 31;
    const int wn = tid >> 5;          // warp -> 16k slice (2 kslices)
    const int bx = blockIdx.x;        // 1024 = 16n x 32t x 2h
    const int n = bx >> 6;
    const int t = (bx >> 1) & 31;
    const int h = bx & 1;

    const uint4* Ub = g_Ufrag;

    // Y[xx][pg][ksl][kk][y]
    float Y[4][2][2][2][4];
#pragma unroll
    for (int xx = 0; xx < 4; xx++)
#pragma unroll
        for (int pg = 0; pg < 2; pg++)
#pragma unroll
            for (int ksl = 0; ksl < 2; ksl++)
#pragma unroll
                for (int kk = 0; kk < 2; kk++)
#pragma unroll
                    for (int y = 0; y < 4; y++) Y[xx][pg][ksl][kk][y] = 0.f;

    // B fragments: double buffer, 2 kslices x 4 ks
    uint4 Bc[2][4], Bn[2][4];
#pragma unroll
    for (int ksl = 0; ksl < 2; ksl++)
#pragma unroll
        for (int ks = 0; ks < 4; ks++)
            Bc[ksl][ks] = __ldg(&Ub[((size_t)(0 * 8 + wn * 2 + ksl) * 4 + ks) * 32 + lane]);

    for (int pass = 0; pass < 2; ++pass) {
        if (pass) __syncthreads();   // mainloop reads of previous planes done

        // ---- phase 1: transform 18 planes (a in [3*pass, 3*pass+3)) ----
        for (int iter = 0; iter < 4; ++iter) {
            int idx = tid + iter * 128;
            int p_l = idx & 15;
            int cp  = idx >> 4;       // c-pair 0..31
            int c0  = cp * 2;
            const float* xb0 = x + ((size_t)(n * C_IN + c0) * H_IN + 4 * t) * W_IN
                                 + (h * 16 + p_l) * 4;
            const float* xb1 = xb0 + (size_t)H_IN * W_IN;

            float t1[2][3][6];
            for (int half = 0; half < 2; half++) {
                const float* xb = half ? xb1 : xb0;
                float d[6][6];
#pragma unroll
                for (int i = 0; i < 6; i++) {
                    float2 v0 = *(const float2*)(xb + i * W_IN + 0);
                    float2 v1 = *(const float2*)(xb + i * W_IN + 2);
                    float2 v2 = *(const float2*)(xb + i * W_IN + 4);
                    d[i][0] = v0.x; d[i][1] = v0.y;
                    d[i][2] = v1.x; d[i][3] = v1.y;
                    d[i][4] = v2.x; d[i][5] = v2.y;
                }
                for (int ar = 0; ar < 3; ar++) {
                    int arow = pass * 3 + ar;
#pragma unroll
                    for (int j = 0; j < 6; j++) {
                        float acc = 0.f;
#pragma unroll
                        for (int i = 0; i < 6; i++)
                            acc += __ldg(&d_BT[arow * 6 + i]) * d[i][j];
                        t1[half][ar][j] = acc;
                    }
                }
            }

            int p_r = p_l & 7;
            uint32_t swb = (uint32_t)((p_l >> 3) * 2048 + p_r * 128)
                         + ((uint32_t)((cp >> 2) ^ p_r) << 4) + (cp & 3) * 4;
            for (int ar = 0; ar < 3; ar++)
                for (int b = 0; b < 6; b++) {
                    float v0 = 0.f, v1 = 0.f;
#pragma unroll
                    for (int j = 0; j < 6; j++) {
                        float bt = __ldg(&d_BT[b * 6 + j]);
                        v0 += t1[0][ar][j] * bt;
                        v1 += t1[1][ar][j] * bt;
                    }
                    float h0 = __bfloat162float(__float2bfloat16_rn(v0));
                    float h1 = __bfloat162float(__float2bfloat16_rn(v1));
                    uint32_t base = (uint32_t)(ar * 6 + b) * 4096u + swb;
                    *(__nv_bfloat162*)(smem + base) = __floats2bfloat162_rn(v0, v1);
                    *(__nv_bfloat162*)(smem + base + 1024u) =
                        __floats2bfloat162_rn(v0 - h0, v1 - h1);
                }
        }
        __syncthreads();

        // ---- mainloop over this pass's 3 a-groups ----
        for (int a2 = 0; a2 < 3; ++a2) {
            const int a = pass * 3 + a2;
            float Z[2][2][2][4];
#pragma unroll
            for (int pg = 0; pg < 2; pg++)
#pragma unroll
                for (int ksl = 0; ksl < 2; ksl++)
#pragma unroll
                    for (int kk = 0; kk < 2; kk++)
#pragma unroll
                        for (int y = 0; y < 4; y++) Z[pg][ksl][kk][y] = 0.f;

            for (int b = 0; b < 6; ++b) {
                const int e = a * 6 + b;
                const int e_l = a2 * 6 + b;
                if (e + 1 < 36) {
#pragma unroll
                    for (int ksl = 0; ksl < 2; ksl++)
#pragma unroll
                        for (int ks = 0; ks < 4; ks++)
                            Bn[ksl][ks] = __ldg(
                                &Ub[((size_t)((e + 1) * 8 + wn * 2 + ksl) * 4 + ks) * 32 + lane]);
                }

                const uint32_t va = sb + (uint32_t)e_l * 4096u;
                float acc[2][2][4];
#pragma unroll
                for (int pg = 0; pg < 2; pg++)
#pragma unroll
                    for (int ksl = 0; ksl < 2; ksl++)
#pragma unroll
                        for (int q = 0; q < 4; q++) acc[pg][ksl][q] = 0.f;

#pragma unroll
                for (int ks = 0; ks < 4; ks++) {
                    uint32_t A0[4], A1[4];
                    int rowA = lane & 15;
                    int colA = (ks * 2 + (lane >> 4)) ^ (rowA & 7);
                    uint32_t aA = va + (uint32_t)(rowA * 128 + colA * 16);
                    LDSM4(A0, aA);
                    LDSM4(A1, aA + 2048u);
#pragma unroll
                    for (int ksl = 0; ksl < 2; ksl++) {
                        const uint4 B = Bc[ksl][ks];
                        MMA_BF16(acc[0][ksl], A0, B.x, B.y);
                        MMA_BF16(acc[0][ksl], A0, B.z, B.w);
                        MMA_BF16(acc[1][ksl], A1, B.x, B.y);
                        MMA_BF16(acc[1][ksl], A1, B.z, B.w);
                    }
                }
                if (e + 1 < 36) {
#pragma unroll
                    for (int ksl = 0; ksl < 2; ksl++)
#pragma unroll
                        for (int ks = 0; ks < 4; ks++) Bc[ksl][ks] = Bn[ksl][ks];
                }

                float cy0 = __ldg(&d_ATC[b]);
                float cy1 = __ldg(&d_ATC[6 + b]);
                float cy2 = __ldg(&d_ATC[12 + b]);
                float cy3 = __ldg(&d_ATC[18 + b]);
#pragma unroll
                for (int pg = 0; pg < 2; pg++)
#pragma unroll
                    for (int ksl = 0; ksl < 2; ksl++) {
                        float m0 = acc[pg][ksl][0] + acc[pg][ksl][2];
                        float m1 = acc[pg][ksl][1] + acc[pg][ksl][3];
                        Z[pg][ksl][0][0] += cy0 * m0; Z[pg][ksl][1][0] += cy0 * m1;
                        Z[pg][ksl][0][1] += cy1 * m0; Z[pg][ksl][1][1] += cy1 * m1;
                        Z[pg][ksl][0][2] += cy2 * m0; Z[pg][ksl][1][2] += cy2 * m1;
                        Z[pg][ksl][0][3] += cy3 * m0; Z[pg][ksl][1][3] += cy3 * m1;
                    }
            }

            float cx0 = __ldg(&d_ATx[a]);
            float cx1 = __ldg(&d_ATx[6 + a]);
            float cx2 = __ldg(&d_ATx[12 + a]);
            float cx3 = __ldg(&d_ATx[18 + a]);
#pragma unroll
            for (int pg = 0; pg < 2; pg++)
#pragma unroll
                for (int ksl = 0; ksl < 2; ksl++)
#pragma unroll
                    for (int kk = 0; kk < 2; kk++)
#pragma unroll
                        for (int y = 0; y < 4; y++) {
                            float z = Z[pg][ksl][kk][y];
                            Y[0][pg][ksl][kk][y] += cx0 * z;
                            Y[1][pg][ksl][kk][y] += cx1 * z;
                            Y[2][pg][ksl][kk][y] += cx2 * z;
                            Y[3][pg][ksl][kk][y] += cx3 * z;
                        }
        }
    }

    // ---- epilogue: direct stores ----
#pragma unroll
    for (int pg = 0; pg < 2; pg++) {
        int s = h * 16 + pg * 8 + (lane >> 2);
#pragma unroll
        for (int ksl = 0; ksl < 2; ksl++)
#pragma unroll
            for (int kk = 0; kk < 2; kk++) {
                int k = wn * 16 + ksl * 8 + (lane & 3) * 2 + kk;
#pragma unroll
                for (int xx = 0; xx < 4; xx++) {
                    float4 v = make_float4(Y[xx][pg][ksl][kk][0], Y[xx][pg][ksl][kk][1],
                                           Y[xx][pg][ksl][kk][2], Y[xx][pg][ksl][kk][3]);
                    *(float4*)&out[((size_t)(n * K_OUT + k) * H_OUT + t * 4 + xx) * H_OUT + s * 4] = v;
                }
            }
    }
}

// ---------------------------------------------------------------------------
extern "C" void kernel_launch(void* const* d_in, const int* in_sizes, int n_in,
                              void* d_out, int out_size) {
    const float* x = (const float*)d_in[0];   // (16,64,130,130)
    const float* w = (const float*)d_in[1];   // (64,64,3,3)
    float* out = (float*)d_out;               // (16,64,128,128)

    cudaFuncSetAttribute(winograd_fused,
                         cudaFuncAttributeMaxDynamicSharedMemorySize, FUSED_SMEM);

    filter_transform<<<dim3(64, 6), 64>>>(w);
    winograd_fused<<<1024, 128, FUSED_SMEM>>>(out, x);
}